// round 7
// baseline (speedup 1.0000x reference)
#include <cuda_runtime.h>
#include <cuda_bf16.h>

// Scratch (device globals — no allocation allowed)
#define NMAX 20000
__device__ __align__(16) float g_ns_acc[NMAX * 64];    // h_ns_int (hs + scattered es)
__device__ __align__(16) float g_nv_acc[NMAX * 192];   // nv_int   (nv1 + scattered ev1)
__device__ __align__(16) float g_nt_norm[NMAX * 64];   // ||nt1||
__device__ __align__(16) float g_mid[NMAX * 96];       // silu(h_cat @ Wc1.T + bc1)

__device__ __forceinline__ float sigm_(float x) { return 1.0f / (1.0f + __expf(-x)); }
__device__ __forceinline__ float silu_(float x) { return x * sigm_(x); }

__device__ __forceinline__ void red_add_v4(float* p, float4 v) {
    asm volatile("red.global.add.v4.f32 [%0], {%1,%2,%3,%4};"
                 :: "l"(p), "f"(v.x), "f"(v.y), "f"(v.z), "f"(v.w) : "memory");
}

// Load W (O x K row-major) into smem transposed: sWt[k*wstride + o]
__device__ __forceinline__ void load_wt(const float* __restrict__ W, float* sWt,
                                        int O, int K, int wstride) {
    for (int i = threadIdx.x; i < O * K; i += blockDim.x) {
        int o = i / K, k = i - o * K;
        sWt[k * wstride + o] = W[i];
    }
}

template<int OPL>
__device__ __forceinline__ void zero8(float (&a)[8][OPL]) {
#pragma unroll
    for (int r = 0; r < 8; r++)
#pragma unroll
        for (int o = 0; o < OPL; o++) a[r][o] = 0.0f;
}

// Software-pipelined warp micro-GEMM: 8 rows x (32*OPL outs).
// Lane owns outs [ocol + OPL*lane .. +OPL). X rows are warp-uniform float4 loads.
// PF = prefetch distance in 4-k steps: X for step ks+PF is loaded BEFORE the
// FMA block of step ks, so gmem latency overlaps FMA issue (kills the
// body-boundary stall that ptxas's front-batched unroll schedule produces).
template<int K, int OPL, bool XG, int PF>
__device__ __forceinline__ void wgemm8p(const float* __restrict__ xbase, int xstride,
                                        const float* __restrict__ sWt, int wstride, int ocol,
                                        float (&acc)[8][OPL], int lane) {
    const int o0 = ocol + OPL * lane;
    constexpr int NS = K / 4;
    float4 xb[PF][8];
#pragma unroll
    for (int s = 0; s < PF && s < NS; s++)
#pragma unroll
        for (int r = 0; r < 8; r++)
            xb[s][r] = XG ? __ldg((const float4*)(xbase + (size_t)r * xstride + s * 4))
                          : *(const float4*)(xbase + (size_t)r * xstride + s * 4);
#pragma unroll
    for (int ks = 0; ks < NS; ks++) {
        const int k = ks * 4;
        // prefetch step ks+PF (issues ahead of this step's FMA block)
        float4 xn[8];
        if (ks + PF < NS) {
#pragma unroll
            for (int r = 0; r < 8; r++)
                xn[r] = XG ? __ldg((const float4*)(xbase + (size_t)r * xstride + k + PF * 4))
                           : *(const float4*)(xbase + (size_t)r * xstride + k + PF * 4);
        }
        float w[4][OPL];
#pragma unroll
        for (int kk = 0; kk < 4; kk++) {
            const float* wp = sWt + (k + kk) * wstride + o0;
            if (OPL == 4) {
                float4 t = *(const float4*)wp;
                w[kk][0] = t.x; w[kk][1] = t.y; w[kk][2] = t.z; w[kk][3] = t.w;
            } else if (OPL == 2) {
                float2 t = *(const float2*)wp;
                w[kk][0] = t.x; w[kk][1] = t.y;
            } else {
                w[kk][0] = *wp;
            }
        }
#pragma unroll
        for (int r = 0; r < 8; r++) {
            float4 x = xb[ks % PF][r];
#pragma unroll
            for (int o = 0; o < OPL; o++)
                acc[r][o] += x.x * w[0][o] + x.y * w[1][o] + x.z * w[2][o] + x.w * w[3][o];
        }
        if (ks + PF < NS) {
#pragma unroll
            for (int r = 0; r < 8; r++) xb[ks % PF][r] = xn[r];
        }
    }
}

// ---------------------------------------------------------------------------
// Kernel A: hs -> g_ns_acc, nv1 -> g_nv_acc, ||nt1|| -> g_nt_norm
// smem: 128*68 + 3*64*68 + 8*512 = 25856 floats (103,424 B)
// ---------------------------------------------------------------------------
#define A_SMEM_BYTES ((128*68 + 64*68 + 64*68 + 64*68 + 8*512) * 4)

__global__ void __launch_bounds__(256, 2) nodeA_kernel(
    const float* __restrict__ h_ns, const float* __restrict__ h_nv,
    const float* __restrict__ h_nt,
    const float* __restrict__ Wns1, const float* __restrict__ bns1,
    const float* __restrict__ Wns2, const float* __restrict__ bns2,
    const float* __restrict__ Wnv1, const float* __restrict__ Wnt1, int N)
{
    extern __shared__ float sm[];
    float* sWns1t = sm;
    float* sWns2t = sWns1t + 128 * 68;
    float* sWnv1t = sWns2t + 64 * 68;
    float* sWnt1t = sWnv1t + 64 * 68;
    float* sBuf   = sWnt1t + 64 * 68;

    load_wt(Wns1, sWns1t, 64, 128, 68);
    load_wt(Wns2, sWns2t, 64, 64, 68);
    load_wt(Wnv1, sWnv1t, 64, 64, 68);
    load_wt(Wnt1, sWnt1t, 64, 64, 68);
    __syncthreads();

    const int lane = threadIdx.x & 31;
    const int warp = threadIdx.x >> 5;
    float* sT = sBuf + warp * 512;

    const float b10 = __ldg(bns1 + 2 * lane), b11 = __ldg(bns1 + 2 * lane + 1);
    const float b20 = __ldg(bns2 + 2 * lane), b21 = __ldg(bns2 + 2 * lane + 1);

    const int gw = blockIdx.x * 8 + warp;
    const int GW = gridDim.x * 8;
    const int ngroups = N >> 3;

    for (int g = gw; g < ngroups; g += GW) {
        const int n0 = g * 8;

        // hs layer 1 (K=128) -> silu -> sT
        float acc[8][2]; zero8(acc);
        wgemm8p<128, 2, true, 2>(h_ns + (size_t)n0 * 128, 128, sWns1t, 68, 0, acc, lane);
        __syncwarp();
#pragma unroll
        for (int r = 0; r < 8; r++) {
            float2 v; v.x = silu_(acc[r][0] + b10); v.y = silu_(acc[r][1] + b11);
            *(float2*)&sT[r * 64 + 2 * lane] = v;
        }
        __syncwarp();

        // hs layer 2 (K=64) -> g_ns_acc
        float acc2[8][2]; zero8(acc2);
        wgemm8p<64, 2, false, 2>(sT, 64, sWns2t, 68, 0, acc2, lane);
#pragma unroll
        for (int r = 0; r < 8; r++) {
            float2 v; v.x = acc2[r][0] + b20; v.y = acc2[r][1] + b21;
            *(float2*)&g_ns_acc[(size_t)(n0 + r) * 64 + 2 * lane] = v;
        }

        // nv1 (3 components) -> g_nv_acc
#pragma unroll 1
        for (int a = 0; a < 3; a++) {
            float acc3[8][2]; zero8(acc3);
            wgemm8p<64, 2, true, 2>(h_nv + (size_t)n0 * 192 + a * 64, 192, sWnv1t, 68, 0, acc3, lane);
#pragma unroll
            for (int r = 0; r < 8; r++) {
                float2 v; v.x = acc3[r][0]; v.y = acc3[r][1];
                *(float2*)&g_nv_acc[(size_t)(n0 + r) * 192 + a * 64 + 2 * lane] = v;
            }
        }

        // ||nt1|| over the 9 (3x3) components
        float sq0[8], sq1[8];
#pragma unroll
        for (int r = 0; r < 8; r++) { sq0[r] = 0.0f; sq1[r] = 0.0f; }
#pragma unroll 1
        for (int c = 0; c < 9; c++) {
            float acc4[8][2]; zero8(acc4);
            wgemm8p<64, 2, true, 2>(h_nt + (size_t)n0 * 576 + c * 64, 576, sWnt1t, 68, 0, acc4, lane);
#pragma unroll
            for (int r = 0; r < 8; r++) {
                sq0[r] += acc4[r][0] * acc4[r][0];
                sq1[r] += acc4[r][1] * acc4[r][1];
            }
        }
#pragma unroll
        for (int r = 0; r < 8; r++) {
            float2 v; v.x = sqrtf(sq0[r]); v.y = sqrtf(sq1[r]);
            *(float2*)&g_nt_norm[(size_t)(n0 + r) * 64 + 2 * lane] = v;
        }
    }
}

// ---------------------------------------------------------------------------
// Edge kernel: es MLP + ev1, scatter-add into g_ns_acc / g_nv_acc
// smem: 128*68 + 2*64*68 + 8*1024 = 25600 floats (102,400 B)
// ---------------------------------------------------------------------------
#define E_SMEM_BYTES ((128*68 + 64*68 + 64*68 + 8*1024) * 4)

__global__ void __launch_bounds__(256, 2) edge_kernel(
    const float* __restrict__ h_es, const float* __restrict__ h_ev,
    const int* __restrict__ idx1, const int* __restrict__ idx2,
    const float* __restrict__ Wes1, const float* __restrict__ bes1,
    const float* __restrict__ Wes2, const float* __restrict__ bes2,
    const float* __restrict__ Wev1, int E)
{
    extern __shared__ float sm[];
    float* sWes1t = sm;
    float* sWes2t = sWes1t + 128 * 68;
    float* sWev1t = sWes2t + 64 * 68;
    float* sBuf   = sWev1t + 64 * 68;

    load_wt(Wes1, sWes1t, 64, 128, 68);
    load_wt(Wes2, sWes2t, 64, 64, 68);
    load_wt(Wev1, sWev1t, 64, 64, 68);
    __syncthreads();

    const int lane = threadIdx.x & 31;
    const int warp = threadIdx.x >> 5;
    float* sT  = sBuf + warp * 1024;
    float* sEs = sT + 512;

    const float b10 = __ldg(bes1 + 2 * lane), b11 = __ldg(bes1 + 2 * lane + 1);
    const float b20 = __ldg(bes2 + 2 * lane), b21 = __ldg(bes2 + 2 * lane + 1);

    const int gw = blockIdx.x * 8 + warp;
    const int GW = gridDim.x * 8;
    const int ngroups = E >> 3;

    for (int g = gw; g < ngroups; g += GW) {
        const int e0 = g * 8;

        // GEMM1: t1 = silu(h_es @ Wes1.T + b) (K=128)
        float acc[8][2]; zero8(acc);
        wgemm8p<128, 2, true, 2>(h_es + (size_t)e0 * 128, 128, sWes1t, 68, 0, acc, lane);
        __syncwarp();
#pragma unroll
        for (int r = 0; r < 8; r++) {
            float2 v; v.x = silu_(acc[r][0] + b10); v.y = silu_(acc[r][1] + b11);
            *(float2*)&sT[r * 64 + 2 * lane] = v;
        }
        __syncwarp();

        // GEMM2: es = t1 @ Wes2.T + b (K=64) -> sEs
        float acc2[8][2]; zero8(acc2);
        wgemm8p<64, 2, false, 2>(sT, 64, sWes2t, 68, 0, acc2, lane);
#pragma unroll
        for (int r = 0; r < 8; r++) {
            float2 v; v.x = acc2[r][0] + b20; v.y = acc2[r][1] + b21;
            *(float2*)&sEs[r * 64 + 2 * lane] = v;
        }
        __syncwarp();

        // scatter es into g_ns_acc at idx1 and idx2 (v4 reds)
#pragma unroll
        for (int j = 0; j < 4; j++) {
            int cid = lane + 32 * j;
            int r = cid >> 4, c = (cid & 15) * 4;
            float4 v = *(const float4*)&sEs[r * 64 + c];
            int i1 = __ldg(idx1 + e0 + r), i2 = __ldg(idx2 + e0 + r);
            red_add_v4(g_ns_acc + (size_t)i1 * 64 + c, v);
            red_add_v4(g_ns_acc + (size_t)i2 * 64 + c, v);
        }

        // ev1 per component, scatter into g_nv_acc
#pragma unroll 1
        for (int a = 0; a < 3; a++) {
            float acc3[8][2]; zero8(acc3);
            wgemm8p<64, 2, true, 2>(h_ev + (size_t)e0 * 192 + a * 64, 192, sWev1t, 68, 0, acc3, lane);
            __syncwarp();
#pragma unroll
            for (int r = 0; r < 8; r++) {
                float2 v; v.x = acc3[r][0]; v.y = acc3[r][1];
                *(float2*)&sEs[r * 64 + 2 * lane] = v;
            }
            __syncwarp();
#pragma unroll
            for (int j = 0; j < 4; j++) {
                int cid = lane + 32 * j;
                int r = cid >> 4, c = (cid & 15) * 4;
                float4 v = *(const float4*)&sEs[r * 64 + c];
                int i1 = __ldg(idx1 + e0 + r), i2 = __ldg(idx2 + e0 + r);
                red_add_v4(g_nv_acc + (size_t)i1 * 192 + a * 64 + c, v);
                red_add_v4(g_nv_acc + (size_t)i2 * 192 + a * 64 + c, v);
            }
        }
    }
}

// ---------------------------------------------------------------------------
// Kernel C1: h_cat = [ns_acc, ||nv_int||, nt_norm]; g_mid = silu(h_cat@Wc1.T+bc1)
// 512 threads (16 warps). smem: 192*100 + 16*1536 = 43776 floats (175,104 B)
// ---------------------------------------------------------------------------
#define C1_SMEM_BYTES ((192*100 + 16*1536) * 4)

__global__ void __launch_bounds__(512, 1) nodeC1_kernel(
    const float* __restrict__ Wc1, const float* __restrict__ bc1, int N)
{
    extern __shared__ float sm[];
    float* sWc1t = sm;
    float* sCatA = sWc1t + 192 * 100;

    load_wt(Wc1, sWc1t, 96, 192, 100);
    __syncthreads();

    const int lane = threadIdx.x & 31;
    const int warp = threadIdx.x >> 5;
    float* cat = sCatA + warp * 1536;

    const float bA0 = __ldg(bc1 + 2 * lane), bA1 = __ldg(bc1 + 2 * lane + 1);
    const float bB  = __ldg(bc1 + 64 + lane);

    const int gw = blockIdx.x * 16 + warp;
    const int GW = gridDim.x * 16;
    const int ngroups = N >> 3;

    for (int g = gw; g < ngroups; g += GW) {
        const int n0 = g * 8;
        __syncwarp();
#pragma unroll
        for (int r = 0; r < 8; r++) {
            const size_t n = (size_t)(n0 + r);
            float2 s = *(const float2*)&g_ns_acc[n * 64 + 2 * lane];
            *(float2*)&cat[r * 192 + 2 * lane] = s;
            float2 v0 = *(const float2*)&g_nv_acc[n * 192 + 0   + 2 * lane];
            float2 v1 = *(const float2*)&g_nv_acc[n * 192 + 64  + 2 * lane];
            float2 v2 = *(const float2*)&g_nv_acc[n * 192 + 128 + 2 * lane];
            float2 nn;
            nn.x = sqrtf(v0.x * v0.x + v1.x * v1.x + v2.x * v2.x);
            nn.y = sqrtf(v0.y * v0.y + v1.y * v1.y + v2.y * v2.y);
            *(float2*)&cat[r * 192 + 64 + 2 * lane] = nn;
            float2 tn = *(const float2*)&g_nt_norm[n * 64 + 2 * lane];
            *(float2*)&cat[r * 192 + 128 + 2 * lane] = tn;
        }
        __syncwarp();

        float accA[8][2]; zero8(accA);
        wgemm8p<192, 2, false, 2>(cat, 192, sWc1t, 100, 0, accA, lane);
        float accB[8][1]; zero8(accB);
        wgemm8p<192, 1, false, 2>(cat, 192, sWc1t, 100, 64, accB, lane);
#pragma unroll
        for (int r = 0; r < 8; r++) {
            const size_t n = (size_t)(n0 + r);
            float2 m; m.x = silu_(accA[r][0] + bA0); m.y = silu_(accA[r][1] + bA1);
            *(float2*)&g_mid[n * 96 + 2 * lane] = m;
            g_mid[n * 96 + 64 + lane] = silu_(accB[r][0] + bB);
        }
    }
}

// ---------------------------------------------------------------------------
// Kernel C2: out = mid@Wc2.T+bc2; fused ns/nv/nt outputs with sigmoid gates
// 512 threads (16 warps). smem: 96*260 + 2*64*68 + 16*1024 = 50048 fl (200,192 B)
// ---------------------------------------------------------------------------
#define C2_SMEM_BYTES ((96*260 + 64*68 + 64*68 + 16*1024) * 4)

__global__ void __launch_bounds__(512, 1) nodeC2_kernel(
    const float* __restrict__ h_ns, const float* __restrict__ h_nv,
    const float* __restrict__ h_nt,
    const float* __restrict__ Wnv2, const float* __restrict__ Wnt2,
    const float* __restrict__ Wc2, const float* __restrict__ bc2,
    float* __restrict__ out, int N)
{
    extern __shared__ float sm[];
    float* sWc2t  = sm;
    float* sWnv2t = sWc2t + 96 * 260;
    float* sWnt2t = sWnv2t + 64 * 68;
    float* sGateA = sWnt2t + 64 * 68;

    load_wt(Wc2, sWc2t, 256, 96, 260);
    load_wt(Wnv2, sWnv2t, 64, 64, 68);
    load_wt(Wnt2, sWnt2t, 64, 64, 68);
    __syncthreads();

    const int lane = threadIdx.x & 31;
    const int warp = threadIdx.x >> 5;
    float* gate = sGateA + warp * 1024;

    float* ns_out = out;
    float* nv_out = out + (size_t)N * 128;
    float* nt_out = out + (size_t)N * 320;

    const float4 bA = __ldg((const float4*)(bc2 + 4 * lane));
    const float4 bB = __ldg((const float4*)(bc2 + 128 + 4 * lane));

    const int gw = blockIdx.x * 16 + warp;
    const int GW = gridDim.x * 16;
    const int ngroups = N >> 3;

    for (int g = gw; g < ngroups; g += GW) {
        const int n0 = g * 8;

        // out cols 0..127 -> ns_out (+ h_ns residual)
        float accA[8][4]; zero8(accA);
        wgemm8p<96, 4, true, 1>(g_mid + (size_t)n0 * 96, 96, sWc2t, 260, 0, accA, lane);
#pragma unroll
        for (int r = 0; r < 8; r++) {
            const size_t n = (size_t)(n0 + r);
            float4 h = __ldg((const float4*)(h_ns + n * 128 + 4 * lane));
            float4 v;
            v.x = accA[r][0] + bA.x + h.x;
            v.y = accA[r][1] + bA.y + h.y;
            v.z = accA[r][2] + bA.z + h.z;
            v.w = accA[r][3] + bA.w + h.w;
            *(float4*)&ns_out[n * 128 + 4 * lane] = v;
        }

        // out cols 128..255 -> gates
        float accB[8][4]; zero8(accB);
        wgemm8p<96, 4, true, 1>(g_mid + (size_t)n0 * 96, 96, sWc2t, 260, 128, accB, lane);
        __syncwarp();
#pragma unroll
        for (int r = 0; r < 8; r++) {
            float4 v;
            v.x = sigm_(accB[r][0] + bB.x);
            v.y = sigm_(accB[r][1] + bB.y);
            v.z = sigm_(accB[r][2] + bB.z);
            v.w = sigm_(accB[r][3] + bB.w);
            *(float4*)&gate[r * 128 + 4 * lane] = v;
        }
        __syncwarp();

        // nv_out = gate_nv * (h_nv @ Wnv2.T) + h_nv
#pragma unroll 1
        for (int a = 0; a < 3; a++) {
            float acc[8][2]; zero8(acc);
            wgemm8p<64, 2, true, 2>(h_nv + (size_t)n0 * 192 + a * 64, 192, sWnv2t, 68, 0, acc, lane);
#pragma unroll
            for (int r = 0; r < 8; r++) {
                const size_t n = (size_t)(n0 + r);
                float2 gt = *(const float2*)&gate[r * 128 + 2 * lane];
                float2 h  = __ldg((const float2*)(h_nv + n * 192 + a * 64 + 2 * lane));
                float2 v;
                v.x = gt.x * acc[r][0] + h.x;
                v.y = gt.y * acc[r][1] + h.y;
                *(float2*)&nv_out[n * 192 + a * 64 + 2 * lane] = v;
            }
        }

        // nt_out = gate_nt * (h_nt @ Wnt2.T) + h_nt
#pragma unroll 1
        for (int c = 0; c < 9; c++) {
            float acc[8][2]; zero8(acc);
            wgemm8p<64, 2, true, 2>(h_nt + (size_t)n0 * 576 + c * 64, 576, sWnt2t, 68, 0, acc, lane);
#pragma unroll
            for (int r = 0; r < 8; r++) {
                const size_t n = (size_t)(n0 + r);
                float2 gt = *(const float2*)&gate[r * 128 + 64 + 2 * lane];
                float2 h  = __ldg((const float2*)(h_nt + n * 576 + c * 64 + 2 * lane));
                float2 v;
                v.x = gt.x * acc[r][0] + h.x;
                v.y = gt.y * acc[r][1] + h.y;
                *(float2*)&nt_out[n * 576 + c * 64 + 2 * lane] = v;
            }
        }
    }
}

// ---------------------------------------------------------------------------
extern "C" void kernel_launch(void* const* d_in, const int* in_sizes, int n_in,
                              void* d_out, int out_size)
{
    const float* h_ns = (const float*)d_in[0];
    const float* h_nv = (const float*)d_in[1];
    const float* h_nt = (const float*)d_in[2];
    const float* h_es = (const float*)d_in[3];
    const float* h_ev = (const float*)d_in[4];
    const int*   idx1 = (const int*)d_in[5];
    const int*   idx2 = (const int*)d_in[6];
    const float* Wns1 = (const float*)d_in[7];
    const float* bns1 = (const float*)d_in[8];
    const float* Wns2 = (const float*)d_in[9];
    const float* bns2 = (const float*)d_in[10];
    const float* Wes1 = (const float*)d_in[11];
    const float* bes1 = (const float*)d_in[12];
    const float* Wes2 = (const float*)d_in[13];
    const float* bes2 = (const float*)d_in[14];
    const float* Wnv1 = (const float*)d_in[15];
    const float* Wnv2 = (const float*)d_in[16];
    const float* Wev1 = (const float*)d_in[17];
    const float* Wnt1 = (const float*)d_in[18];
    const float* Wnt2 = (const float*)d_in[19];
    const float* Wc1  = (const float*)d_in[20];
    const float* bc1  = (const float*)d_in[21];
    const float* Wc2  = (const float*)d_in[22];
    const float* bc2  = (const float*)d_in[23];
    float* out = (float*)d_out;

    const int N = in_sizes[0] / 128;   // h_ns is (N, 128)
    const int E = in_sizes[5];         // atom_index1 is (E,)

    cudaFuncSetAttribute(nodeA_kernel,  cudaFuncAttributeMaxDynamicSharedMemorySize, A_SMEM_BYTES);
    cudaFuncSetAttribute(edge_kernel,   cudaFuncAttributeMaxDynamicSharedMemorySize, E_SMEM_BYTES);
    cudaFuncSetAttribute(nodeC1_kernel, cudaFuncAttributeMaxDynamicSharedMemorySize, C1_SMEM_BYTES);
    cudaFuncSetAttribute(nodeC2_kernel, cudaFuncAttributeMaxDynamicSharedMemorySize, C2_SMEM_BYTES);

    nodeA_kernel<<<304, 256, A_SMEM_BYTES>>>(
        h_ns, h_nv, h_nt, Wns1, bns1, Wns2, bns2, Wnv1, Wnt1, N);

    edge_kernel<<<304, 256, E_SMEM_BYTES>>>(
        h_es, h_ev, idx1, idx2, Wes1, bes1, Wes2, bes2, Wev1, E);

    nodeC1_kernel<<<152, 512, C1_SMEM_BYTES>>>(Wc1, bc1, N);

    nodeC2_kernel<<<152, 512, C2_SMEM_BYTES>>>(
        h_ns, h_nv, h_nt, Wnv2, Wnt2, Wc2, bc2, out, N);
}

// round 8
// speedup vs baseline: 1.4502x; 1.4502x over previous
#include <cuda_runtime.h>
#include <cuda_bf16.h>

// Scratch (device globals — no allocation allowed)
#define NMAX 20000
__device__ __align__(16) float g_ns_acc[NMAX * 64];    // h_ns_int (hs + scattered es)
__device__ __align__(16) float g_nv_acc[NMAX * 192];   // nv_int   (nv1 + scattered ev1)
__device__ __align__(16) float g_nt_norm[NMAX * 64];   // ||nt1||
__device__ __align__(16) float g_mid[NMAX * 96];       // silu(h_cat @ Wc1.T + bc1)

__device__ __forceinline__ float sigm_(float x) { return 1.0f / (1.0f + __expf(-x)); }
__device__ __forceinline__ float silu_(float x) { return x * sigm_(x); }

__device__ __forceinline__ void red_add_v4(float* p, float4 v) {
    asm volatile("red.global.add.v4.f32 [%0], {%1,%2,%3,%4};"
                 :: "l"(p), "f"(v.x), "f"(v.y), "f"(v.z), "f"(v.w) : "memory");
}

// Load W (O x K row-major) into smem transposed: sWt[k*wstride + o]
__device__ __forceinline__ void load_wt(const float* __restrict__ W, float* sWt,
                                        int O, int K, int wstride) {
    for (int i = threadIdx.x; i < O * K; i += blockDim.x) {
        int o = i / K, k = i - o * K;
        sWt[k * wstride + o] = W[i];
    }
}

// Same, but for W rows [o_begin, o_begin+O)
__device__ __forceinline__ void load_wt_part(const float* __restrict__ W, float* sWt,
                                             int o_begin, int O, int K, int wstride) {
    for (int i = threadIdx.x; i < O * K; i += blockDim.x) {
        int o = i / K, k = i - o * K;
        sWt[k * wstride + o] = W[(size_t)(o_begin + o) * K + k];
    }
}

template<int OPL>
__device__ __forceinline__ void zero8(float (&a)[8][OPL]) {
#pragma unroll
    for (int r = 0; r < 8; r++)
#pragma unroll
        for (int o = 0; o < OPL; o++) a[r][o] = 0.0f;
}

// Warp micro-GEMM (R5 proven version): 8 rows x (32*OPL outs).
// Lane owns outs [ocol + OPL*lane .. +OPL). X rows warp-uniform loads.
template<int K, int OPL, bool XG>
__device__ __forceinline__ void wgemm8(const float* __restrict__ xbase, int xstride,
                                       const float* __restrict__ sWt, int wstride, int ocol,
                                       float (&acc)[8][OPL], int lane) {
    const int o0 = ocol + OPL * lane;
#pragma unroll 4
    for (int k = 0; k < K; k += 4) {
        float w[4][OPL];
#pragma unroll
        for (int kk = 0; kk < 4; kk++) {
            const float* wp = sWt + (k + kk) * wstride + o0;
            if (OPL == 4) {
                float4 t = *(const float4*)wp;
                w[kk][0] = t.x; w[kk][1] = t.y; w[kk][2] = t.z; w[kk][3] = t.w;
            } else if (OPL == 2) {
                float2 t = *(const float2*)wp;
                w[kk][0] = t.x; w[kk][1] = t.y;
            } else {
                w[kk][0] = *wp;
            }
        }
#pragma unroll
        for (int r = 0; r < 8; r++) {
            float4 x;
            if (XG) x = __ldg((const float4*)(xbase + (size_t)r * xstride + k));
            else    x = *(const float4*)(xbase + (size_t)r * xstride + k);
#pragma unroll
            for (int o = 0; o < OPL; o++)
                acc[r][o] += x.x * w[0][o] + x.y * w[1][o] + x.z * w[2][o] + x.w * w[3][o];
        }
    }
}

// ---------------------------------------------------------------------------
// Kernel A: hs -> g_ns_acc, nv1 -> g_nv_acc, ||nt1|| -> g_nt_norm   (R5)
// ---------------------------------------------------------------------------
#define A_SMEM_BYTES ((128*68 + 64*68 + 64*68 + 64*68 + 8*512) * 4)

__global__ void __launch_bounds__(256, 2) nodeA_kernel(
    const float* __restrict__ h_ns, const float* __restrict__ h_nv,
    const float* __restrict__ h_nt,
    const float* __restrict__ Wns1, const float* __restrict__ bns1,
    const float* __restrict__ Wns2, const float* __restrict__ bns2,
    const float* __restrict__ Wnv1, const float* __restrict__ Wnt1, int N)
{
    extern __shared__ float sm[];
    float* sWns1t = sm;
    float* sWns2t = sWns1t + 128 * 68;
    float* sWnv1t = sWns2t + 64 * 68;
    float* sWnt1t = sWnv1t + 64 * 68;
    float* sBuf   = sWnt1t + 64 * 68;

    load_wt(Wns1, sWns1t, 64, 128, 68);
    load_wt(Wns2, sWns2t, 64, 64, 68);
    load_wt(Wnv1, sWnv1t, 64, 64, 68);
    load_wt(Wnt1, sWnt1t, 64, 64, 68);
    __syncthreads();

    const int lane = threadIdx.x & 31;
    const int warp = threadIdx.x >> 5;
    float* sT = sBuf + warp * 512;

    const float b10 = __ldg(bns1 + 2 * lane), b11 = __ldg(bns1 + 2 * lane + 1);
    const float b20 = __ldg(bns2 + 2 * lane), b21 = __ldg(bns2 + 2 * lane + 1);

    const int gw = blockIdx.x * 8 + warp;
    const int GW = gridDim.x * 8;
    const int ngroups = N >> 3;

    for (int g = gw; g < ngroups; g += GW) {
        const int n0 = g * 8;

        float acc[8][2]; zero8(acc);
        wgemm8<128, 2, true>(h_ns + (size_t)n0 * 128, 128, sWns1t, 68, 0, acc, lane);
        __syncwarp();
#pragma unroll
        for (int r = 0; r < 8; r++) {
            float2 v; v.x = silu_(acc[r][0] + b10); v.y = silu_(acc[r][1] + b11);
            *(float2*)&sT[r * 64 + 2 * lane] = v;
        }
        __syncwarp();

        float acc2[8][2]; zero8(acc2);
        wgemm8<64, 2, false>(sT, 64, sWns2t, 68, 0, acc2, lane);
#pragma unroll
        for (int r = 0; r < 8; r++) {
            float2 v; v.x = acc2[r][0] + b20; v.y = acc2[r][1] + b21;
            *(float2*)&g_ns_acc[(size_t)(n0 + r) * 64 + 2 * lane] = v;
        }

#pragma unroll 1
        for (int a = 0; a < 3; a++) {
            float acc3[8][2]; zero8(acc3);
            wgemm8<64, 2, true>(h_nv + (size_t)n0 * 192 + a * 64, 192, sWnv1t, 68, 0, acc3, lane);
#pragma unroll
            for (int r = 0; r < 8; r++) {
                float2 v; v.x = acc3[r][0]; v.y = acc3[r][1];
                *(float2*)&g_nv_acc[(size_t)(n0 + r) * 192 + a * 64 + 2 * lane] = v;
            }
        }

        float sq0[8], sq1[8];
#pragma unroll
        for (int r = 0; r < 8; r++) { sq0[r] = 0.0f; sq1[r] = 0.0f; }
#pragma unroll 1
        for (int c = 0; c < 9; c++) {
            float acc4[8][2]; zero8(acc4);
            wgemm8<64, 2, true>(h_nt + (size_t)n0 * 576 + c * 64, 576, sWnt1t, 68, 0, acc4, lane);
#pragma unroll
            for (int r = 0; r < 8; r++) {
                sq0[r] += acc4[r][0] * acc4[r][0];
                sq1[r] += acc4[r][1] * acc4[r][1];
            }
        }
#pragma unroll
        for (int r = 0; r < 8; r++) {
            float2 v; v.x = sqrtf(sq0[r]); v.y = sqrtf(sq1[r]);
            *(float2*)&g_nt_norm[(size_t)(n0 + r) * 64 + 2 * lane] = v;
        }
    }
}

// ---------------------------------------------------------------------------
// Edge kernel: es MLP + ev1, scatter-add into g_ns_acc / g_nv_acc   (R5)
// ---------------------------------------------------------------------------
#define E_SMEM_BYTES ((128*68 + 64*68 + 64*68 + 8*1024) * 4)

__global__ void __launch_bounds__(256, 2) edge_kernel(
    const float* __restrict__ h_es, const float* __restrict__ h_ev,
    const int* __restrict__ idx1, const int* __restrict__ idx2,
    const float* __restrict__ Wes1, const float* __restrict__ bes1,
    const float* __restrict__ Wes2, const float* __restrict__ bes2,
    const float* __restrict__ Wev1, int E)
{
    extern __shared__ float sm[];
    float* sWes1t = sm;
    float* sWes2t = sWes1t + 128 * 68;
    float* sWev1t = sWes2t + 64 * 68;
    float* sBuf   = sWev1t + 64 * 68;

    load_wt(Wes1, sWes1t, 64, 128, 68);
    load_wt(Wes2, sWes2t, 64, 64, 68);
    load_wt(Wev1, sWev1t, 64, 64, 68);
    __syncthreads();

    const int lane = threadIdx.x & 31;
    const int warp = threadIdx.x >> 5;
    float* sT  = sBuf + warp * 1024;
    float* sEs = sT + 512;

    const float b10 = __ldg(bes1 + 2 * lane), b11 = __ldg(bes1 + 2 * lane + 1);
    const float b20 = __ldg(bes2 + 2 * lane), b21 = __ldg(bes2 + 2 * lane + 1);

    const int gw = blockIdx.x * 8 + warp;
    const int GW = gridDim.x * 8;
    const int ngroups = E >> 3;

    for (int g = gw; g < ngroups; g += GW) {
        const int e0 = g * 8;

        float acc[8][2]; zero8(acc);
        wgemm8<128, 2, true>(h_es + (size_t)e0 * 128, 128, sWes1t, 68, 0, acc, lane);
        __syncwarp();
#pragma unroll
        for (int r = 0; r < 8; r++) {
            float2 v; v.x = silu_(acc[r][0] + b10); v.y = silu_(acc[r][1] + b11);
            *(float2*)&sT[r * 64 + 2 * lane] = v;
        }
        __syncwarp();

        float acc2[8][2]; zero8(acc2);
        wgemm8<64, 2, false>(sT, 64, sWes2t, 68, 0, acc2, lane);
#pragma unroll
        for (int r = 0; r < 8; r++) {
            float2 v; v.x = acc2[r][0] + b20; v.y = acc2[r][1] + b21;
            *(float2*)&sEs[r * 64 + 2 * lane] = v;
        }
        __syncwarp();

#pragma unroll
        for (int j = 0; j < 4; j++) {
            int cid = lane + 32 * j;
            int r = cid >> 4, c = (cid & 15) * 4;
            float4 v = *(const float4*)&sEs[r * 64 + c];
            int i1 = __ldg(idx1 + e0 + r), i2 = __ldg(idx2 + e0 + r);
            red_add_v4(g_ns_acc + (size_t)i1 * 64 + c, v);
            red_add_v4(g_ns_acc + (size_t)i2 * 64 + c, v);
        }

#pragma unroll 1
        for (int a = 0; a < 3; a++) {
            float acc3[8][2]; zero8(acc3);
            wgemm8<64, 2, true>(h_ev + (size_t)e0 * 192 + a * 64, 192, sWev1t, 68, 0, acc3, lane);
            __syncwarp();
#pragma unroll
            for (int r = 0; r < 8; r++) {
                float2 v; v.x = acc3[r][0]; v.y = acc3[r][1];
                *(float2*)&sEs[r * 64 + 2 * lane] = v;
            }
            __syncwarp();
#pragma unroll
            for (int j = 0; j < 4; j++) {
                int cid = lane + 32 * j;
                int r = cid >> 4, c = (cid & 15) * 4;
                float4 v = *(const float4*)&sEs[r * 64 + c];
                int i1 = __ldg(idx1 + e0 + r), i2 = __ldg(idx2 + e0 + r);
                red_add_v4(g_nv_acc + (size_t)i1 * 192 + a * 64 + c, v);
                red_add_v4(g_nv_acc + (size_t)i2 * 192 + a * 64 + c, v);
            }
        }
    }
}

// ---------------------------------------------------------------------------
// Kernel C1: h_cat = [ns_acc, ||nv_int||, nt_norm]; g_mid = silu(h_cat@Wc1.T+bc1)
// (R5: 256 threads, 1 CTA/SM by smem)
// ---------------------------------------------------------------------------
#define C1_SMEM_BYTES ((192*100 + 8*1536) * 4)

__global__ void __launch_bounds__(256, 1) nodeC1_kernel(
    const float* __restrict__ Wc1, const float* __restrict__ bc1, int N)
{
    extern __shared__ float sm[];
    float* sWc1t = sm;
    float* sCatA = sWc1t + 192 * 100;

    load_wt(Wc1, sWc1t, 96, 192, 100);
    __syncthreads();

    const int lane = threadIdx.x & 31;
    const int warp = threadIdx.x >> 5;
    float* cat = sCatA + warp * 1536;

    const float bA0 = __ldg(bc1 + 2 * lane), bA1 = __ldg(bc1 + 2 * lane + 1);
    const float bB  = __ldg(bc1 + 64 + lane);

    const int gw = blockIdx.x * 8 + warp;
    const int GW = gridDim.x * 8;
    const int ngroups = N >> 3;

    for (int g = gw; g < ngroups; g += GW) {
        const int n0 = g * 8;
        __syncwarp();
#pragma unroll
        for (int r = 0; r < 8; r++) {
            const size_t n = (size_t)(n0 + r);
            float2 s = *(const float2*)&g_ns_acc[n * 64 + 2 * lane];
            *(float2*)&cat[r * 192 + 2 * lane] = s;
            float2 v0 = *(const float2*)&g_nv_acc[n * 192 + 0   + 2 * lane];
            float2 v1 = *(const float2*)&g_nv_acc[n * 192 + 64  + 2 * lane];
            float2 v2 = *(const float2*)&g_nv_acc[n * 192 + 128 + 2 * lane];
            float2 nn;
            nn.x = sqrtf(v0.x * v0.x + v1.x * v1.x + v2.x * v2.x);
            nn.y = sqrtf(v0.y * v0.y + v1.y * v1.y + v2.y * v2.y);
            *(float2*)&cat[r * 192 + 64 + 2 * lane] = nn;
            float2 tn = *(const float2*)&g_nt_norm[n * 64 + 2 * lane];
            *(float2*)&cat[r * 192 + 128 + 2 * lane] = tn;
        }
        __syncwarp();

        float accA[8][2]; zero8(accA);
        wgemm8<192, 2, false>(cat, 192, sWc1t, 100, 0, accA, lane);
        float accB[8][1]; zero8(accB);
        wgemm8<192, 1, false>(cat, 192, sWc1t, 100, 64, accB, lane);
#pragma unroll
        for (int r = 0; r < 8; r++) {
            const size_t n = (size_t)(n0 + r);
            float2 m; m.x = silu_(accA[r][0] + bA0); m.y = silu_(accA[r][1] + bA1);
            *(float2*)&g_mid[n * 96 + 2 * lane] = m;
            g_mid[n * 96 + 64 + lane] = silu_(accB[r][0] + bB);
        }
    }
}

// ---------------------------------------------------------------------------
// Kernel C2a: ns_out = g_mid @ Wc2[0:128].T + bc2[0:128] + h_ns
// smem: 96*132 = 12672 fl (50.7 KB) -> 2 CTAs/SM; OPL=2 keeps regs low
// ---------------------------------------------------------------------------
#define C2A_SMEM_BYTES ((96*132) * 4)

__global__ void __launch_bounds__(256, 2) nodeC2a_kernel(
    const float* __restrict__ h_ns,
    const float* __restrict__ Wc2, const float* __restrict__ bc2,
    float* __restrict__ out, int N)
{
    extern __shared__ float sm[];
    float* sW = sm;   // Wc2 rows 0..127 transposed, stride 132 (local cols 0..127)

    load_wt_part(Wc2, sW, 0, 128, 96, 132);
    __syncthreads();

    const int lane = threadIdx.x & 31;
    const int warp = threadIdx.x >> 5;

    const float b0 = __ldg(bc2 + 2 * lane),      b1 = __ldg(bc2 + 2 * lane + 1);
    const float b2 = __ldg(bc2 + 64 + 2 * lane), b3 = __ldg(bc2 + 64 + 2 * lane + 1);

    const int gw = blockIdx.x * 8 + warp;
    const int GW = gridDim.x * 8;
    const int ngroups = N >> 3;

    for (int g = gw; g < ngroups; g += GW) {
        const int n0 = g * 8;
        const float* mid = g_mid + (size_t)n0 * 96;

        float accA[8][2]; zero8(accA);
        wgemm8<96, 2, true>(mid, 96, sW, 132, 0, accA, lane);
        float accB[8][2]; zero8(accB);
        wgemm8<96, 2, true>(mid, 96, sW, 132, 64, accB, lane);

#pragma unroll
        for (int r = 0; r < 8; r++) {
            const size_t n = (size_t)(n0 + r);
            float2 hA = __ldg((const float2*)(h_ns + n * 128 + 2 * lane));
            float2 hB = __ldg((const float2*)(h_ns + n * 128 + 64 + 2 * lane));
            float2 vA, vB;
            vA.x = accA[r][0] + b0 + hA.x;
            vA.y = accA[r][1] + b1 + hA.y;
            vB.x = accB[r][0] + b2 + hB.x;
            vB.y = accB[r][1] + b3 + hB.y;
            *(float2*)&out[n * 128 + 2 * lane] = vA;
            *(float2*)&out[n * 128 + 64 + 2 * lane] = vB;
        }
    }
}

// ---------------------------------------------------------------------------
// Kernel C2b: gates = sigmoid(g_mid @ Wc2[128:256].T + bc2[128:256]);
//             nv_out = gate_nv * (h_nv@Wnv2.T) + h_nv; nt_out likewise.
// Gates live in registers (lane's gate cols == its nv/nt output cols).
// smem: 96*132 + 2*64*68 = 21376 fl (85.5 KB) -> 2 CTAs/SM
// ---------------------------------------------------------------------------
#define C2B_SMEM_BYTES ((96*132 + 64*68 + 64*68) * 4)

__global__ void __launch_bounds__(256, 2) nodeC2b_kernel(
    const float* __restrict__ h_nv, const float* __restrict__ h_nt,
    const float* __restrict__ Wnv2, const float* __restrict__ Wnt2,
    const float* __restrict__ Wc2, const float* __restrict__ bc2,
    float* __restrict__ out, int N)
{
    extern __shared__ float sm[];
    float* sWg   = sm;                 // Wc2 rows 128..255 transposed, stride 132
    float* sWnv2 = sWg + 96 * 132;
    float* sWnt2 = sWnv2 + 64 * 68;

    load_wt_part(Wc2, sWg, 128, 128, 96, 132);
    load_wt(Wnv2, sWnv2, 64, 64, 68);
    load_wt(Wnt2, sWnt2, 64, 64, 68);
    __syncthreads();

    const int lane = threadIdx.x & 31;
    const int warp = threadIdx.x >> 5;

    float* nv_out = out + (size_t)N * 128;
    float* nt_out = out + (size_t)N * 320;

    const float bn0 = __ldg(bc2 + 128 + 2 * lane), bn1 = __ldg(bc2 + 128 + 2 * lane + 1);
    const float bt0 = __ldg(bc2 + 192 + 2 * lane), bt1 = __ldg(bc2 + 192 + 2 * lane + 1);

    const int gw = blockIdx.x * 8 + warp;
    const int GW = gridDim.x * 8;
    const int ngroups = N >> 3;

    for (int g = gw; g < ngroups; g += GW) {
        const int n0 = g * 8;
        const float* mid = g_mid + (size_t)n0 * 96;

        // gate_nv: out cols 128..191 (local 0..63). Lane -> cols {2l, 2l+1}.
        float gA[8][2]; zero8(gA);
        wgemm8<96, 2, true>(mid, 96, sWg, 132, 0, gA, lane);
#pragma unroll
        for (int r = 0; r < 8; r++) {
            gA[r][0] = sigm_(gA[r][0] + bn0);
            gA[r][1] = sigm_(gA[r][1] + bn1);
        }

        // nv_out = gate_nv * (h_nv @ Wnv2.T) + h_nv  (3 components)
#pragma unroll 1
        for (int a = 0; a < 3; a++) {
            float acc[8][2]; zero8(acc);
            wgemm8<64, 2, true>(h_nv + (size_t)n0 * 192 + a * 64, 192, sWnv2, 68, 0, acc, lane);
#pragma unroll
            for (int r = 0; r < 8; r++) {
                const size_t n = (size_t)(n0 + r);
                float2 h = __ldg((const float2*)(h_nv + n * 192 + a * 64 + 2 * lane));
                float2 v;
                v.x = gA[r][0] * acc[r][0] + h.x;
                v.y = gA[r][1] * acc[r][1] + h.y;
                *(float2*)&nv_out[n * 192 + a * 64 + 2 * lane] = v;
            }
        }

        // gate_nt: out cols 192..255 (local 64..127). Lane -> cols {2l, 2l+1}.
        float gB[8][2]; zero8(gB);
        wgemm8<96, 2, true>(mid, 96, sWg, 132, 64, gB, lane);
#pragma unroll
        for (int r = 0; r < 8; r++) {
            gB[r][0] = sigm_(gB[r][0] + bt0);
            gB[r][1] = sigm_(gB[r][1] + bt1);
        }

        // nt_out = gate_nt * (h_nt @ Wnt2.T) + h_nt  (9 components)
#pragma unroll 1
        for (int c = 0; c < 9; c++) {
            float acc[8][2]; zero8(acc);
            wgemm8<64, 2, true>(h_nt + (size_t)n0 * 576 + c * 64, 576, sWnt2, 68, 0, acc, lane);
#pragma unroll
            for (int r = 0; r < 8; r++) {
                const size_t n = (size_t)(n0 + r);
                float2 h = __ldg((const float2*)(h_nt + n * 576 + c * 64 + 2 * lane));
                float2 v;
                v.x = gB[r][0] * acc[r][0] + h.x;
                v.y = gB[r][1] * acc[r][1] + h.y;
                *(float2*)&nt_out[n * 576 + c * 64 + 2 * lane] = v;
            }
        }
    }
}

// ---------------------------------------------------------------------------
extern "C" void kernel_launch(void* const* d_in, const int* in_sizes, int n_in,
                              void* d_out, int out_size)
{
    const float* h_ns = (const float*)d_in[0];
    const float* h_nv = (const float*)d_in[1];
    const float* h_nt = (const float*)d_in[2];
    const float* h_es = (const float*)d_in[3];
    const float* h_ev = (const float*)d_in[4];
    const int*   idx1 = (const int*)d_in[5];
    const int*   idx2 = (const int*)d_in[6];
    const float* Wns1 = (const float*)d_in[7];
    const float* bns1 = (const float*)d_in[8];
    const float* Wns2 = (const float*)d_in[9];
    const float* bns2 = (const float*)d_in[10];
    const float* Wes1 = (const float*)d_in[11];
    const float* bes1 = (const float*)d_in[12];
    const float* Wes2 = (const float*)d_in[13];
    const float* bes2 = (const float*)d_in[14];
    const float* Wnv1 = (const float*)d_in[15];
    const float* Wnv2 = (const float*)d_in[16];
    const float* Wev1 = (const float*)d_in[17];
    const float* Wnt1 = (const float*)d_in[18];
    const float* Wnt2 = (const float*)d_in[19];
    const float* Wc1  = (const float*)d_in[20];
    const float* bc1  = (const float*)d_in[21];
    const float* Wc2  = (const float*)d_in[22];
    const float* bc2  = (const float*)d_in[23];
    float* out = (float*)d_out;

    const int N = in_sizes[0] / 128;   // h_ns is (N, 128)
    const int E = in_sizes[5];         // atom_index1 is (E,)

    cudaFuncSetAttribute(nodeA_kernel,   cudaFuncAttributeMaxDynamicSharedMemorySize, A_SMEM_BYTES);
    cudaFuncSetAttribute(edge_kernel,    cudaFuncAttributeMaxDynamicSharedMemorySize, E_SMEM_BYTES);
    cudaFuncSetAttribute(nodeC1_kernel,  cudaFuncAttributeMaxDynamicSharedMemorySize, C1_SMEM_BYTES);
    cudaFuncSetAttribute(nodeC2a_kernel, cudaFuncAttributeMaxDynamicSharedMemorySize, C2A_SMEM_BYTES);
    cudaFuncSetAttribute(nodeC2b_kernel, cudaFuncAttributeMaxDynamicSharedMemorySize, C2B_SMEM_BYTES);

    nodeA_kernel<<<304, 256, A_SMEM_BYTES>>>(
        h_ns, h_nv, h_nt, Wns1, bns1, Wns2, bns2, Wnv1, Wnt1, N);

    edge_kernel<<<304, 256, E_SMEM_BYTES>>>(
        h_es, h_ev, idx1, idx2, Wes1, bes1, Wes2, bes2, Wev1, E);

    nodeC1_kernel<<<152, 256, C1_SMEM_BYTES>>>(Wc1, bc1, N);

    nodeC2a_kernel<<<304, 256, C2A_SMEM_BYTES>>>(h_ns, Wc2, bc2, out, N);

    nodeC2b_kernel<<<304, 256, C2B_SMEM_BYTES>>>(
        h_nv, h_nt, Wnv2, Wnt2, Wc2, bc2, out, N);
}